// round 1
// baseline (speedup 1.0000x reference)
#include <cuda_runtime.h>

#define FULLMASK 0xffffffffu

// Accumulator: per (node, channel) 10 components (sI, wA*3, M*6) padded to 12.
// 20000 * 32 * 12 * 4B = 30.72 MB — fits in L2 (126 MB).
__device__ __align__(16) float g_acc[20000 * 32 * 12];

__device__ __forceinline__ void red_add_v4(float* a, float x, float y, float z, float w) {
    asm volatile("red.global.add.v4.f32 [%0], {%1,%2,%3,%4};"
                 :: "l"(a), "f"(x), "f"(y), "f"(z), "f"(w) : "memory");
}
__device__ __forceinline__ void red_add_v2(float* a, float x, float y) {
    asm volatile("red.global.add.v2.f32 [%0], {%1,%2};"
                 :: "l"(a), "f"(x), "f"(y) : "memory");
}

__global__ void zero_kernel(int n4) {
    float4* p = reinterpret_cast<float4*>(g_acc);
    float4 z = make_float4(0.f, 0.f, 0.f, 0.f);
    for (int i = blockIdx.x * blockDim.x + threadIdx.x; i < n4; i += gridDim.x * blockDim.x)
        p[i] = z;
}

// edge_feat = edge_attr @ Wemb3 + bemb3. Warp processes 4 edges, lane = out channel.
__global__ __launch_bounds__(256) void ef_kernel(
    const float* __restrict__ ea, const float* __restrict__ We3,
    const float* __restrict__ be3, float* __restrict__ out, int E)
{
    __shared__ float Ws[64 * 32];
    __shared__ float bs[32];
    int tid = threadIdx.x;
    for (int i = tid; i < 64 * 32; i += 256) Ws[i] = We3[i];
    if (tid < 32) bs[tid] = be3[tid];
    __syncthreads();
    const int u = tid & 31;
    int gw = blockIdx.x * 8 + (tid >> 5);
    int nw = gridDim.x * 8;
    int ngroups = (E + 3) >> 2;
    for (int g = gw; g < ngroups; g += nw) {
        int e0 = g * 4;
        float a0[4], a1[4], acc[4];
#pragma unroll
        for (int j = 0; j < 4; j++) {
            int e = min(e0 + j, E - 1);
            a0[j] = ea[(size_t)e * 64 + u];
            a1[j] = ea[(size_t)e * 64 + 32 + u];
            acc[j] = bs[u];
        }
#pragma unroll 8
        for (int k = 0; k < 32; k++) {
            float w = Ws[k * 32 + u];
            float w2 = Ws[(k + 32) * 32 + u];
#pragma unroll
            for (int j = 0; j < 4; j++) {
                acc[j] = fmaf(__shfl_sync(FULLMASK, a0[j], k), w, acc[j]);
                acc[j] = fmaf(__shfl_sync(FULLMASK, a1[j], k), w2, acc[j]);
            }
        }
#pragma unroll
        for (int j = 0; j < 4; j++) {
            int e = e0 + j;
            if (e < E) out[(size_t)e * 32 + u] = acc[j];
        }
    }
}

// Edge phase: 4 GEMVs 64->32 per edge + geometry, then vector-red into g_acc.
// Warp = 4 edges, lane = channel u. Weights packed as float2 pairs in smem.
__global__ __launch_bounds__(256) void edge_kernel(
    const float* __restrict__ ea, const float* __restrict__ bdist,
    const float* __restrict__ bvec, const int* __restrict__ src,
    const int* __restrict__ dst, const int* __restrict__ ntype,
    const float* __restrict__ emb,
    const float* __restrict__ Wd1, const float* __restrict__ bd1,
    const float* __restrict__ Wd2, const float* __restrict__ bd2,
    const float* __restrict__ Wd3, const float* __restrict__ bd3,
    const float* __restrict__ We2, const float* __restrict__ be2,
    int E, int ntypes)
{
    __shared__ float2 Wa[64 * 32];   // (Wd1, Wd2)[k][u]
    __shared__ float2 Wb[64 * 32];   // (Wd3, We2)[k][u]
    __shared__ float Zs[96 * 32];    // embedding table (95 types)
    __shared__ float b1s[32], b2s[32], b3s[32], be2s[32];
    int tid = threadIdx.x;
    for (int i = tid; i < 64 * 32; i += 256) {
        Wa[i] = make_float2(Wd1[i], Wd2[i]);
        Wb[i] = make_float2(Wd3[i], We2[i]);
    }
    for (int i = tid; i < ntypes * 32; i += 256) Zs[i] = emb[i];
    if (tid < 32) { b1s[tid] = bd1[tid]; b2s[tid] = bd2[tid]; b3s[tid] = bd3[tid]; be2s[tid] = be2[tid]; }
    __syncthreads();
    const int u = tid & 31;
    int gw = blockIdx.x * 8 + (tid >> 5);
    int nw = gridDim.x * 8;
    int ngroups = (E + 3) >> 2;
    for (int g = gw; g < ngroups; g += nw) {
        int e0 = g * 4;
        float a0[4], a1[4], zsv[4], zdv[4];
        float vx[4], vy[4], vz[4], Cc[4];
        int dn[4];
#pragma unroll
        for (int j = 0; j < 4; j++) {
            int e = min(e0 + j, E - 1);
            a0[j] = ea[(size_t)e * 64 + u];
            a1[j] = ea[(size_t)e * 64 + 32 + u];
            int s = src[e], d = dst[e];
            dn[j] = d;
            zsv[j] = Zs[ntype[s] * 32 + u];
            zdv[j] = Zs[ntype[d] * 32 + u];
            float dd = bdist[e];
            float c = 0.5f * (__cosf(0.62831853071795864769f * dd) + 1.f);  // pi/CUTOFF
            Cc[j] = (dd <= 5.0f) ? c : 0.f;
            float bx = bvec[(size_t)e * 3], by = bvec[(size_t)e * 3 + 1], bz = bvec[(size_t)e * 3 + 2];
            float inv = rsqrtf(bx * bx + by * by + bz * bz);
            vx[j] = bx * inv; vy[j] = by * inv; vz[j] = bz * inv;
        }
        float w1[4], w2[4], w3[4], zj[4];
#pragma unroll
        for (int j = 0; j < 4; j++) { w1[j] = b1s[u]; w2[j] = b2s[u]; w3[j] = b3s[u]; zj[j] = be2s[u]; }
#pragma unroll 8
        for (int k = 0; k < 32; k++) {
            float2 wa = Wa[k * 32 + u];
            float2 wb = Wb[k * 32 + u];
#pragma unroll
            for (int j = 0; j < 4; j++) {
                float a = __shfl_sync(FULLMASK, a0[j], k);
                float z = __shfl_sync(FULLMASK, zsv[j], k);
                w1[j] = fmaf(a, wa.x, w1[j]);
                w2[j] = fmaf(a, wa.y, w2[j]);
                w3[j] = fmaf(a, wb.x, w3[j]);
                zj[j] = fmaf(z, wb.y, zj[j]);
            }
        }
#pragma unroll 8
        for (int k = 0; k < 32; k++) {
            float2 wa = Wa[(k + 32) * 32 + u];
            float2 wb = Wb[(k + 32) * 32 + u];
#pragma unroll
            for (int j = 0; j < 4; j++) {
                float a = __shfl_sync(FULLMASK, a1[j], k);
                float z = __shfl_sync(FULLMASK, zdv[j], k);
                w1[j] = fmaf(a, wa.x, w1[j]);
                w2[j] = fmaf(a, wa.y, w2[j]);
                w3[j] = fmaf(a, wb.x, w3[j]);
                zj[j] = fmaf(z, wb.y, zj[j]);
            }
        }
#pragma unroll
        for (int j = 0; j < 4; j++) {
            int e = e0 + j;
            if (e >= E) break;
            float fI = zj[j] * w1[j] * Cc[j];
            float p  = zj[j] * w2[j] * Cc[j];
            float q  = zj[j] * w3[j] * Cc[j];
            float* base = g_acc + ((size_t)dn[j] * 32 + u) * 12;
            red_add_v4(base,     fI,                 p * vx[j],          p * vy[j],          p * vz[j]);
            red_add_v4(base + 4, q * vx[j] * vx[j],  q * vy[j] * vy[j],  q * vz[j] * vz[j],  q * vx[j] * vy[j]);
            red_add_v2(base + 8, q * vx[j] * vz[j],  q * vy[j] * vz[j]);
        }
    }
}

// Node epilogue: norm, LayerNorm, MLP, channel mixing, reconstruct X[n,u,3,3].
// Warp per node, lane = channel.
__global__ __launch_bounds__(256) void node_kernel(
    const float* __restrict__ Ws1, const float* __restrict__ bs1,
    const float* __restrict__ Ws2, const float* __restrict__ bs2,
    const float* __restrict__ Wt0, const float* __restrict__ Wt1, const float* __restrict__ Wt2,
    const float* __restrict__ lng, const float* __restrict__ lnb,
    float* __restrict__ outX, int N)
{
    __shared__ float Ws1s[32 * 64];
    __shared__ float Ws2s[64 * 96];
    __shared__ float Wt0s[32 * 32], Wt1s[32 * 32], Wt2s[32 * 32];
    __shared__ float bs1s[64], bs2s[96], lngs[32], lnbs[32];
    __shared__ float wbuf[8][64];
    int tid = threadIdx.x;
    for (int i = tid; i < 32 * 64; i += 256) Ws1s[i] = Ws1[i];
    for (int i = tid; i < 64 * 96; i += 256) Ws2s[i] = Ws2[i];
    for (int i = tid; i < 32 * 32; i += 256) { Wt0s[i] = Wt0[i]; Wt1s[i] = Wt1[i]; Wt2s[i] = Wt2[i]; }
    if (tid < 64) bs1s[tid] = bs1[tid];
    if (tid < 96) bs2s[tid] = bs2[tid];
    if (tid < 32) { lngs[tid] = lng[tid]; lnbs[tid] = lnb[tid]; }
    __syncthreads();
    const int u = tid & 31, w = tid >> 5;
    float* wb = wbuf[w];
    int gw = blockIdx.x * 8 + w, nw = gridDim.x * 8;
    for (int n = gw; n < N; n += nw) {
        const float* base = g_acc + ((size_t)n * 32 + u) * 12;
        float4 A0 = *reinterpret_cast<const float4*>(base);
        float4 A1 = *reinterpret_cast<const float4*>(base + 4);
        float2 A2 = *reinterpret_cast<const float2*>(base + 8);
        float sI = A0.x, wx = A0.y, wy = A0.z, wz = A0.w;
        float Mxx = A1.x, Myy = A1.y, Mzz = A1.z, Mxy = A1.w, Mxz = A2.x, Myz = A2.y;
        float trM = Mxx + Myy + Mzz;
        float dg = sI - trM * (1.f / 3.f);
        float t00 = dg + Mxx, t11 = dg + Myy, t22 = dg + Mzz;
        // ||sI*I + skew(wA) + (M - trM/3 I)||_F^2
        float nr = t00 * t00 + t11 * t11 + t22 * t22
                 + 2.f * (Mxy * Mxy + wz * wz + Mxz * Mxz + wy * wy + Myz * Myz + wx * wx);
        // LayerNorm over 32 channels (warp)
        float s = nr;
#pragma unroll
        for (int o = 16; o; o >>= 1) s += __shfl_xor_sync(FULLMASK, s, o);
        float mu = s * (1.f / 32.f);
        float dv = nr - mu;
        float v2 = dv * dv;
#pragma unroll
        for (int o = 16; o; o >>= 1) v2 += __shfl_xor_sync(FULLMASK, v2, o);
        float y = dv * rsqrtf(v2 * (1.f / 32.f) + 1e-5f) * lngs[u] + lnbs[u];
        wb[u] = y;
        __syncwarp();
        // MLP layer 1: [32] -> [64], silu
        float h1a = bs1s[u], h1b = bs1s[u + 32];
#pragma unroll 8
        for (int k = 0; k < 32; k++) {
            float t = wb[k];
            h1a = fmaf(t, Ws1s[k * 64 + u], h1a);
            h1b = fmaf(t, Ws1s[k * 64 + u + 32], h1b);
        }
        h1a = h1a / (1.f + __expf(-h1a));
        h1b = h1b / (1.f + __expf(-h1b));
        __syncwarp();
        wb[u] = h1a; wb[u + 32] = h1b;
        __syncwarp();
        // MLP layer 2: [64] -> [96], silu; lane u owns outputs 3u..3u+2
        float s0 = bs2s[3 * u], s1 = bs2s[3 * u + 1], s2 = bs2s[3 * u + 2];
#pragma unroll 8
        for (int k = 0; k < 64; k++) {
            float t = wb[k];
            s0 = fmaf(t, Ws2s[k * 96 + 3 * u], s0);
            s1 = fmaf(t, Ws2s[k * 96 + 3 * u + 1], s1);
            s2 = fmaf(t, Ws2s[k * 96 + 3 * u + 2], s2);
        }
        s0 = s0 / (1.f + __expf(-s0));
        s1 = s1 / (1.f + __expf(-s1));
        s2 = s2 / (1.f + __expf(-s2));
        // Channel mixing (pre-LN sums): out[v] = sum_u in[u] * Wt[u][v]
        float pI = 0, px = 0, py = 0, pz = 0, pxx = 0, pyy = 0, pzz = 0, pxy = 0, pxz = 0, pyz = 0;
#pragma unroll 4
        for (int k = 0; k < 32; k++) {
            float w0v = Wt0s[k * 32 + u], w1v = Wt1s[k * 32 + u], w2v = Wt2s[k * 32 + u];
            pI  = fmaf(__shfl_sync(FULLMASK, sI,  k), w0v, pI);
            px  = fmaf(__shfl_sync(FULLMASK, wx,  k), w1v, px);
            py  = fmaf(__shfl_sync(FULLMASK, wy,  k), w1v, py);
            pz  = fmaf(__shfl_sync(FULLMASK, wz,  k), w1v, pz);
            pxx = fmaf(__shfl_sync(FULLMASK, Mxx, k), w2v, pxx);
            pyy = fmaf(__shfl_sync(FULLMASK, Myy, k), w2v, pyy);
            pzz = fmaf(__shfl_sync(FULLMASK, Mzz, k), w2v, pzz);
            pxy = fmaf(__shfl_sync(FULLMASK, Mxy, k), w2v, pxy);
            pxz = fmaf(__shfl_sync(FULLMASK, Mxz, k), w2v, pxz);
            pyz = fmaf(__shfl_sync(FULLMASK, Myz, k), w2v, pyz);
        }
        float t3 = (pxx + pyy + pzz) * (1.f / 3.f);
        float* o = outX + ((size_t)n * 32 + u) * 9;
        o[0] =  s0 * pI + s2 * (pxx - t3);
        o[1] = -s1 * pz + s2 * pxy;
        o[2] =  s1 * py + s2 * pxz;
        o[3] =  s1 * pz + s2 * pxy;
        o[4] =  s0 * pI + s2 * (pyy - t3);
        o[5] = -s1 * px + s2 * pyz;
        o[6] = -s1 * py + s2 * pxz;
        o[7] =  s1 * px + s2 * pyz;
        o[8] =  s0 * pI + s2 * (pzz - t3);
        __syncwarp();
    }
}

extern "C" void kernel_launch(void* const* d_in, const int* in_sizes, int n_in,
                              void* d_out, int out_size) {
    (void)n_in; (void)out_size;
    const int*   node_type = (const int*)d_in[0];
    const float* edge_attr = (const float*)d_in[1];
    const float* bond_dist = (const float*)d_in[2];
    const float* bond_vec  = (const float*)d_in[3];
    const int*   src = (const int*)d_in[4];
    const int*   dst = (const int*)d_in[5];
    const float* emb = (const float*)d_in[6];
    const float* Wd1 = (const float*)d_in[7];  const float* bd1 = (const float*)d_in[8];
    const float* Wd2 = (const float*)d_in[9];  const float* bd2 = (const float*)d_in[10];
    const float* Wd3 = (const float*)d_in[11]; const float* bd3 = (const float*)d_in[12];
    const float* We2 = (const float*)d_in[13]; const float* be2 = (const float*)d_in[14];
    const float* We3 = (const float*)d_in[15]; const float* be3 = (const float*)d_in[16];
    const float* Wt0 = (const float*)d_in[17];
    const float* Wt1 = (const float*)d_in[18];
    const float* Wt2 = (const float*)d_in[19];
    const float* Ws1 = (const float*)d_in[20]; const float* bs1 = (const float*)d_in[21];
    const float* Ws2 = (const float*)d_in[22]; const float* bs2 = (const float*)d_in[23];
    const float* lng = (const float*)d_in[24]; const float* lnb = (const float*)d_in[25];

    int N = in_sizes[0];
    int E = in_sizes[2];
    int ntypes = in_sizes[6] / 32;
    float* outX  = (float*)d_out;
    float* outEF = outX + (size_t)N * 32 * 9;

    zero_kernel<<<1024, 256>>>(N * 96);                   // N*32*12/4 float4s
    ef_kernel<<<592, 256>>>(edge_attr, We3, be3, outEF, E);
    edge_kernel<<<592, 256>>>(edge_attr, bond_dist, bond_vec, src, dst, node_type,
                              emb, Wd1, bd1, Wd2, bd2, Wd3, bd3, We2, be2, E, ntypes);
    node_kernel<<<250, 256>>>(Ws1, bs1, Ws2, bs2, Wt0, Wt1, Wt2, lng, lnb, outX, N);
}

// round 2
// speedup vs baseline: 1.4876x; 1.4876x over previous
#include <cuda_runtime.h>

#define FULLMASK 0xffffffffu

// ---------------- persistent device scratch ----------------
// Accumulator: per (node, channel) 10 components (sI, wA*3, M*6) padded to 12.
__device__ __align__(16) float g_acc[20000 * 32 * 12];     // 30.7 MB
__device__ float g_ZhS[95 * 32];                           // emb @ We2[:32]
__device__ float g_ZhD[95 * 32];                           // emb @ We2[32:]
__device__ float g_ptab[95 * 95 * 32];                     // 1.15 MB, L2-hot
__device__ int   g_pidx[200000];
__device__ __align__(16) float4 g_geo[200000];             // (C, vx, vy, vz)

__device__ __forceinline__ void red_add_v4(float* a, float x, float y, float z, float w) {
    asm volatile("red.global.add.v4.f32 [%0], {%1,%2,%3,%4};"
                 :: "l"(a), "f"(x), "f"(y), "f"(z), "f"(w) : "memory");
}
__device__ __forceinline__ void red_add_v2(float* a, float x, float y) {
    asm volatile("red.global.add.v2.f32 [%0], {%1,%2};"
                 :: "l"(a), "f"(x), "f"(y) : "memory");
}

// ---------------- tiny precompute kernels ----------------
// Zh half-products: one block per type, 64 threads (lane<32: src half, else dst half)
__global__ void zh_kernel(const float* __restrict__ emb, const float* __restrict__ We2,
                          int ntypes) {
    int t = blockIdx.x;
    if (t >= ntypes) return;
    int u = threadIdx.x & 31;
    int half = threadIdx.x >> 5;
    float s = 0.f;
#pragma unroll 8
    for (int k = 0; k < 32; k++)
        s = fmaf(emb[t * 32 + k], We2[(k + half * 32) * 32 + u], s);
    (half ? g_ZhD : g_ZhS)[t * 32 + u] = s;
}

// pair table: warp per (ts, td) pair
__global__ __launch_bounds__(256) void ptab_kernel(const float* __restrict__ be2, int ntypes) {
    int w = blockIdx.x * 8 + (threadIdx.x >> 5);
    int npairs = ntypes * ntypes;
    if (w >= npairs) return;
    int u = threadIdx.x & 31;
    int ts = w / ntypes, td = w - ts * ntypes;
    g_ptab[w * 32 + u] = g_ZhS[ts * 32 + u] + g_ZhD[td * 32 + u] + be2[u];
}

// prep: zero accumulator + per-edge pair index + geometry (coalesced)
__global__ void prep_kernel(const int* __restrict__ src, const int* __restrict__ dst,
                            const int* __restrict__ ntype,
                            const float* __restrict__ bdist, const float* __restrict__ bvec,
                            int N, int E, int ntypes) {
    int stride = gridDim.x * blockDim.x;
    int g = blockIdx.x * blockDim.x + threadIdx.x;
    int n4 = N * 96;   // N*32*12 floats / 4
    float4* acc4 = reinterpret_cast<float4*>(g_acc);
    float4 z = make_float4(0.f, 0.f, 0.f, 0.f);
    for (int i = g; i < n4; i += stride) acc4[i] = z;
    for (int e = g; e < E; e += stride) {
        g_pidx[e] = ntype[src[e]] * ntypes + ntype[dst[e]];
        float dd = bdist[e];
        float c = 0.5f * (__cosf(0.62831853071795864769f * dd) + 1.f);
        c = (dd <= 5.0f) ? c : 0.f;
        float bx = bvec[(size_t)e * 3], by = bvec[(size_t)e * 3 + 1], bz = bvec[(size_t)e * 3 + 2];
        float inv = rsqrtf(bx * bx + by * by + bz * bz);
        g_geo[e] = make_float4(c, bx * inv, by * inv, bz * inv);
    }
}

// ---------------- edge phase (fused ef) ----------------
// Warp = 4 edges, lane = channel u. Per edge: 3 cutoff-GEMVs + ef-GEMV (shared
// shfl broadcasts), Zij from L2 pair table, vector-red into g_acc.
__global__ __launch_bounds__(256) void edge_kernel(
    const float* __restrict__ ea, const int* __restrict__ dst,
    const float* __restrict__ Wd1, const float* __restrict__ bd1,
    const float* __restrict__ Wd2, const float* __restrict__ bd2,
    const float* __restrict__ Wd3, const float* __restrict__ bd3,
    const float* __restrict__ We3, const float* __restrict__ be3,
    float* __restrict__ outEF, int E)
{
    __shared__ float2 Wa[64 * 32];   // (Wd1, Wd2)[k][u]
    __shared__ float2 Wb[64 * 32];   // (Wd3, We3)[k][u]
    __shared__ float b1s[32], b2s[32], b3s[32], be3s[32];
    int tid = threadIdx.x;
    for (int i = tid; i < 64 * 32; i += 256) {
        Wa[i] = make_float2(Wd1[i], Wd2[i]);
        Wb[i] = make_float2(Wd3[i], We3[i]);
    }
    if (tid < 32) { b1s[tid] = bd1[tid]; b2s[tid] = bd2[tid]; b3s[tid] = bd3[tid]; be3s[tid] = be3[tid]; }
    __syncthreads();
    const int u = tid & 31;
    int gw = blockIdx.x * 8 + (tid >> 5);
    int nw = gridDim.x * 8;
    int ngroups = (E + 3) >> 2;
    for (int g = gw; g < ngroups; g += nw) {
        int e0 = g * 4;
        float a0[4], a1[4], zj[4];
        float4 geo[4];
        int dn[4];
#pragma unroll
        for (int j = 0; j < 4; j++) {
            int e = min(e0 + j, E - 1);
            a0[j] = ea[(size_t)e * 64 + u];
            a1[j] = ea[(size_t)e * 64 + 32 + u];
            dn[j] = dst[e];
            geo[j] = g_geo[e];
            zj[j] = g_ptab[(size_t)g_pidx[e] * 32 + u];
        }
        float w1[4], w2[4], w3[4], ef[4];
#pragma unroll
        for (int j = 0; j < 4; j++) { w1[j] = b1s[u]; w2[j] = b2s[u]; w3[j] = b3s[u]; ef[j] = be3s[u]; }
#pragma unroll 8
        for (int k = 0; k < 32; k++) {
            float2 wa = Wa[k * 32 + u];
            float2 wb = Wb[k * 32 + u];
#pragma unroll
            for (int j = 0; j < 4; j++) {
                float a = __shfl_sync(FULLMASK, a0[j], k);
                w1[j] = fmaf(a, wa.x, w1[j]);
                w2[j] = fmaf(a, wa.y, w2[j]);
                w3[j] = fmaf(a, wb.x, w3[j]);
                ef[j] = fmaf(a, wb.y, ef[j]);
            }
        }
#pragma unroll 8
        for (int k = 0; k < 32; k++) {
            float2 wa = Wa[(k + 32) * 32 + u];
            float2 wb = Wb[(k + 32) * 32 + u];
#pragma unroll
            for (int j = 0; j < 4; j++) {
                float a = __shfl_sync(FULLMASK, a1[j], k);
                w1[j] = fmaf(a, wa.x, w1[j]);
                w2[j] = fmaf(a, wa.y, w2[j]);
                w3[j] = fmaf(a, wb.x, w3[j]);
                ef[j] = fmaf(a, wb.y, ef[j]);
            }
        }
#pragma unroll
        for (int j = 0; j < 4; j++) {
            int e = e0 + j;
            if (e >= E) break;
            outEF[(size_t)e * 32 + u] = ef[j];
            float C = geo[j].x, vx = geo[j].y, vy = geo[j].z, vz = geo[j].w;
            float fI = zj[j] * w1[j] * C;
            float p  = zj[j] * w2[j] * C;
            float q  = zj[j] * w3[j] * C;
            float* base = g_acc + ((size_t)dn[j] * 32 + u) * 12;
            red_add_v4(base,     fI,           p * vx,       p * vy,       p * vz);
            red_add_v4(base + 4, q * vx * vx,  q * vy * vy,  q * vz * vz,  q * vx * vy);
            red_add_v2(base + 8, q * vx * vz,  q * vy * vz);
        }
    }
}

// ---------------- node epilogue ----------------
__global__ __launch_bounds__(256) void node_kernel(
    const float* __restrict__ Ws1, const float* __restrict__ bs1,
    const float* __restrict__ Ws2, const float* __restrict__ bs2,
    const float* __restrict__ Wt0, const float* __restrict__ Wt1, const float* __restrict__ Wt2,
    const float* __restrict__ lng, const float* __restrict__ lnb,
    float* __restrict__ outX, int N)
{
    __shared__ float Ws1s[32 * 64];
    __shared__ float Ws2s[64 * 96];
    __shared__ float Wt0s[32 * 32], Wt1s[32 * 32], Wt2s[32 * 32];
    __shared__ float bs1s[64], bs2s[96], lngs[32], lnbs[32];
    __shared__ float wbuf[8][64];
    int tid = threadIdx.x;
    for (int i = tid; i < 32 * 64; i += 256) Ws1s[i] = Ws1[i];
    for (int i = tid; i < 64 * 96; i += 256) Ws2s[i] = Ws2[i];
    for (int i = tid; i < 32 * 32; i += 256) { Wt0s[i] = Wt0[i]; Wt1s[i] = Wt1[i]; Wt2s[i] = Wt2[i]; }
    if (tid < 64) bs1s[tid] = bs1[tid];
    if (tid < 96) bs2s[tid] = bs2[tid];
    if (tid < 32) { lngs[tid] = lng[tid]; lnbs[tid] = lnb[tid]; }
    __syncthreads();
    const int u = tid & 31, w = tid >> 5;
    float* wb = wbuf[w];
    int gw = blockIdx.x * 8 + w, nw = gridDim.x * 8;
    for (int n = gw; n < N; n += nw) {
        const float* base = g_acc + ((size_t)n * 32 + u) * 12;
        float4 A0 = *reinterpret_cast<const float4*>(base);
        float4 A1 = *reinterpret_cast<const float4*>(base + 4);
        float2 A2 = *reinterpret_cast<const float2*>(base + 8);
        float sI = A0.x, wx = A0.y, wy = A0.z, wz = A0.w;
        float Mxx = A1.x, Myy = A1.y, Mzz = A1.z, Mxy = A1.w, Mxz = A2.x, Myz = A2.y;
        float trM = Mxx + Myy + Mzz;
        float dg = sI - trM * (1.f / 3.f);
        float t00 = dg + Mxx, t11 = dg + Myy, t22 = dg + Mzz;
        float nr = t00 * t00 + t11 * t11 + t22 * t22
                 + 2.f * (Mxy * Mxy + wz * wz + Mxz * Mxz + wy * wy + Myz * Myz + wx * wx);
        float s = nr;
#pragma unroll
        for (int o = 16; o; o >>= 1) s += __shfl_xor_sync(FULLMASK, s, o);
        float mu = s * (1.f / 32.f);
        float dv = nr - mu;
        float v2 = dv * dv;
#pragma unroll
        for (int o = 16; o; o >>= 1) v2 += __shfl_xor_sync(FULLMASK, v2, o);
        float y = dv * rsqrtf(v2 * (1.f / 32.f) + 1e-5f) * lngs[u] + lnbs[u];
        wb[u] = y;
        __syncwarp();
        float h1a = bs1s[u], h1b = bs1s[u + 32];
#pragma unroll 8
        for (int k = 0; k < 32; k++) {
            float t = wb[k];
            h1a = fmaf(t, Ws1s[k * 64 + u], h1a);
            h1b = fmaf(t, Ws1s[k * 64 + u + 32], h1b);
        }
        h1a = h1a / (1.f + __expf(-h1a));
        h1b = h1b / (1.f + __expf(-h1b));
        __syncwarp();
        wb[u] = h1a; wb[u + 32] = h1b;
        __syncwarp();
        float s0 = bs2s[3 * u], s1 = bs2s[3 * u + 1], s2 = bs2s[3 * u + 2];
#pragma unroll 8
        for (int k = 0; k < 64; k++) {
            float t = wb[k];
            s0 = fmaf(t, Ws2s[k * 96 + 3 * u], s0);
            s1 = fmaf(t, Ws2s[k * 96 + 3 * u + 1], s1);
            s2 = fmaf(t, Ws2s[k * 96 + 3 * u + 2], s2);
        }
        s0 = s0 / (1.f + __expf(-s0));
        s1 = s1 / (1.f + __expf(-s1));
        s2 = s2 / (1.f + __expf(-s2));
        float pI = 0, px = 0, py = 0, pz = 0, pxx = 0, pyy = 0, pzz = 0, pxy = 0, pxz = 0, pyz = 0;
#pragma unroll 4
        for (int k = 0; k < 32; k++) {
            float w0v = Wt0s[k * 32 + u], w1v = Wt1s[k * 32 + u], w2v = Wt2s[k * 32 + u];
            pI  = fmaf(__shfl_sync(FULLMASK, sI,  k), w0v, pI);
            px  = fmaf(__shfl_sync(FULLMASK, wx,  k), w1v, px);
            py  = fmaf(__shfl_sync(FULLMASK, wy,  k), w1v, py);
            pz  = fmaf(__shfl_sync(FULLMASK, wz,  k), w1v, pz);
            pxx = fmaf(__shfl_sync(FULLMASK, Mxx, k), w2v, pxx);
            pyy = fmaf(__shfl_sync(FULLMASK, Myy, k), w2v, pyy);
            pzz = fmaf(__shfl_sync(FULLMASK, Mzz, k), w2v, pzz);
            pxy = fmaf(__shfl_sync(FULLMASK, Mxy, k), w2v, pxy);
            pxz = fmaf(__shfl_sync(FULLMASK, Mxz, k), w2v, pxz);
            pyz = fmaf(__shfl_sync(FULLMASK, Myz, k), w2v, pyz);
        }
        float t3 = (pxx + pyy + pzz) * (1.f / 3.f);
        float* o = outX + ((size_t)n * 32 + u) * 9;
        o[0] =  s0 * pI + s2 * (pxx - t3);
        o[1] = -s1 * pz + s2 * pxy;
        o[2] =  s1 * py + s2 * pxz;
        o[3] =  s1 * pz + s2 * pxy;
        o[4] =  s0 * pI + s2 * (pyy - t3);
        o[5] = -s1 * px + s2 * pyz;
        o[6] = -s1 * py + s2 * pxz;
        o[7] =  s1 * px + s2 * pyz;
        o[8] =  s0 * pI + s2 * (pzz - t3);
        __syncwarp();
    }
}

extern "C" void kernel_launch(void* const* d_in, const int* in_sizes, int n_in,
                              void* d_out, int out_size) {
    (void)n_in; (void)out_size;
    const int*   node_type = (const int*)d_in[0];
    const float* edge_attr = (const float*)d_in[1];
    const float* bond_dist = (const float*)d_in[2];
    const float* bond_vec  = (const float*)d_in[3];
    const int*   src = (const int*)d_in[4];
    const int*   dst = (const int*)d_in[5];
    const float* emb = (const float*)d_in[6];
    const float* Wd1 = (const float*)d_in[7];  const float* bd1 = (const float*)d_in[8];
    const float* Wd2 = (const float*)d_in[9];  const float* bd2 = (const float*)d_in[10];
    const float* Wd3 = (const float*)d_in[11]; const float* bd3 = (const float*)d_in[12];
    const float* We2 = (const float*)d_in[13]; const float* be2 = (const float*)d_in[14];
    const float* We3 = (const float*)d_in[15]; const float* be3 = (const float*)d_in[16];
    const float* Wt0 = (const float*)d_in[17];
    const float* Wt1 = (const float*)d_in[18];
    const float* Wt2 = (const float*)d_in[19];
    const float* Ws1 = (const float*)d_in[20]; const float* bs1 = (const float*)d_in[21];
    const float* Ws2 = (const float*)d_in[22]; const float* bs2 = (const float*)d_in[23];
    const float* lng = (const float*)d_in[24]; const float* lnb = (const float*)d_in[25];

    int N = in_sizes[0];
    int E = in_sizes[2];
    int ntypes = in_sizes[6] / 32;
    float* outX  = (float*)d_out;
    float* outEF = outX + (size_t)N * 32 * 9;

    zh_kernel<<<ntypes, 64>>>(emb, We2, ntypes);
    ptab_kernel<<<(ntypes * ntypes + 7) / 8, 256>>>(be2, ntypes);
    prep_kernel<<<1024, 256>>>(src, dst, node_type, bond_dist, bond_vec, N, E, ntypes);
    edge_kernel<<<592, 256>>>(edge_attr, dst, Wd1, bd1, Wd2, bd2, Wd3, bd3,
                              We3, be3, outEF, E);
    node_kernel<<<592, 256>>>(Ws1, bs1, Ws2, bs2, Wt0, Wt1, Wt2, lng, lnb, outX, N);
}

// round 3
// speedup vs baseline: 1.5281x; 1.0272x over previous
#include <cuda_runtime.h>

#define FULLMASK 0xffffffffu

// ---------------- persistent device scratch ----------------
__device__ __align__(16) float g_acc[20000 * 32 * 12];     // 30.7 MB
__device__ float g_ZhS[95 * 32];
__device__ float g_ZhD[95 * 32];
__device__ float g_ptab[95 * 95 * 32];                     // 1.15 MB, L2-hot
__device__ int   g_pidx[200000];
__device__ __align__(16) float4 g_geo[200000];             // (C, vx, vy, vz)

__device__ __forceinline__ void red_add_v4(float* a, float x, float y, float z, float w) {
    asm volatile("red.global.add.v4.f32 [%0], {%1,%2,%3,%4};"
                 :: "l"(a), "f"(x), "f"(y), "f"(z), "f"(w) : "memory");
}
__device__ __forceinline__ void red_add_v2(float* a, float x, float y) {
    asm volatile("red.global.add.v2.f32 [%0], {%1,%2};"
                 :: "l"(a), "f"(x), "f"(y) : "memory");
}
// packed fp32x2 FMA (sm_100+): d = a*b + c elementwise on both halves
__device__ __forceinline__ float2 ffma2(float2 a, float2 b, float2 c) {
    float2 d;
    asm("fma.rn.f32x2 %0, %1, %2, %3;"
        : "=l"(*(unsigned long long*)&d)
        : "l"(*(unsigned long long*)&a),
          "l"(*(unsigned long long*)&b),
          "l"(*(unsigned long long*)&c));
    return d;
}

// ---------------- tiny precompute kernels ----------------
__global__ void zh_kernel(const float* __restrict__ emb, const float* __restrict__ We2,
                          int ntypes) {
    int t = blockIdx.x;
    if (t >= ntypes) return;
    int u = threadIdx.x & 31;
    int half = threadIdx.x >> 5;
    float s = 0.f;
#pragma unroll 8
    for (int k = 0; k < 32; k++)
        s = fmaf(emb[t * 32 + k], We2[(k + half * 32) * 32 + u], s);
    (half ? g_ZhD : g_ZhS)[t * 32 + u] = s;
}

__global__ __launch_bounds__(256) void ptab_kernel(const float* __restrict__ be2, int ntypes) {
    int w = blockIdx.x * 8 + (threadIdx.x >> 5);
    int npairs = ntypes * ntypes;
    if (w >= npairs) return;
    int u = threadIdx.x & 31;
    int ts = w / ntypes, td = w - ts * ntypes;
    g_ptab[w * 32 + u] = g_ZhS[ts * 32 + u] + g_ZhD[td * 32 + u] + be2[u];
}

__global__ void prep_kernel(const int* __restrict__ src, const int* __restrict__ dst,
                            const int* __restrict__ ntype,
                            const float* __restrict__ bdist, const float* __restrict__ bvec,
                            int N, int E, int ntypes) {
    int stride = gridDim.x * blockDim.x;
    int g = blockIdx.x * blockDim.x + threadIdx.x;
    int n4 = N * 96;
    float4* acc4 = reinterpret_cast<float4*>(g_acc);
    float4 z = make_float4(0.f, 0.f, 0.f, 0.f);
    for (int i = g; i < n4; i += stride) acc4[i] = z;
    for (int e = g; e < E; e += stride) {
        g_pidx[e] = ntype[src[e]] * ntypes + ntype[dst[e]];
        float dd = bdist[e];
        float c = 0.5f * (__cosf(0.62831853071795864769f * dd) + 1.f);
        c = (dd <= 5.0f) ? c : 0.f;
        float bx = bvec[(size_t)e * 3], by = bvec[(size_t)e * 3 + 1], bz = bvec[(size_t)e * 3 + 2];
        float inv = rsqrtf(bx * bx + by * by + bz * bz);
        g_geo[e] = make_float4(c, bx * inv, by * inv, bz * inv);
    }
}

// ---------------- edge phase ----------------
// Warp = 8 edges, lane = channel u. Accumulators packed f32x2 across edge pairs.
// Per k-iter: 2 LDS.64 + 4 dup-MOV + 8 SHFL + 16 FFMA2 covers 8 edges x 4 GEMVs.
__global__ __launch_bounds__(256, 2) void edge_kernel(
    const float* __restrict__ ea, const int* __restrict__ dst,
    const float* __restrict__ Wd1, const float* __restrict__ bd1,
    const float* __restrict__ Wd2, const float* __restrict__ bd2,
    const float* __restrict__ Wd3, const float* __restrict__ bd3,
    const float* __restrict__ We3, const float* __restrict__ be3,
    float* __restrict__ outEF, int E)
{
    __shared__ float2 Wa[64 * 32];   // (Wd1, Wd2)[k][u]
    __shared__ float2 Wb[64 * 32];   // (Wd3, We3)[k][u]
    __shared__ float b1s[32], b2s[32], b3s[32], be3s[32];
    int tid = threadIdx.x;
    for (int i = tid; i < 64 * 32; i += 256) {
        Wa[i] = make_float2(Wd1[i], Wd2[i]);
        Wb[i] = make_float2(Wd3[i], We3[i]);
    }
    if (tid < 32) { b1s[tid] = bd1[tid]; b2s[tid] = bd2[tid]; b3s[tid] = bd3[tid]; be3s[tid] = be3[tid]; }
    __syncthreads();
    const int u = tid & 31;
    int gw = blockIdx.x * 8 + (tid >> 5);
    int nw = gridDim.x * 8;
    int ngroups = (E + 7) >> 3;
    for (int g = gw; g < ngroups; g += nw) {
        int e0 = g * 8;
        float a0[8], a1[8], zj[8];
        float4 geo[8];
        int dn[8];
#pragma unroll
        for (int j = 0; j < 8; j++) {
            int e = min(e0 + j, E - 1);
            a0[j] = ea[(size_t)e * 64 + u];
            a1[j] = ea[(size_t)e * 64 + 32 + u];
            dn[j] = dst[e];
            geo[j] = g_geo[e];
            zj[j] = g_ptab[(size_t)g_pidx[e] * 32 + u];
        }
        float2 w1[4], w2[4], w3[4], ef[4];
        {
            float b1 = b1s[u], b2 = b2s[u], b3 = b3s[u], be = be3s[u];
#pragma unroll
            for (int p = 0; p < 4; p++) {
                w1[p] = make_float2(b1, b1);
                w2[p] = make_float2(b2, b2);
                w3[p] = make_float2(b3, b3);
                ef[p] = make_float2(be, be);
            }
        }
#pragma unroll 4
        for (int k = 0; k < 32; k++) {
            float2 wa = Wa[k * 32 + u];
            float2 wb = Wb[k * 32 + u];
            float2 d1 = make_float2(wa.x, wa.x);
            float2 d2 = make_float2(wa.y, wa.y);
            float2 d3 = make_float2(wb.x, wb.x);
            float2 de = make_float2(wb.y, wb.y);
#pragma unroll
            for (int p = 0; p < 4; p++) {
                float2 ap;
                ap.x = __shfl_sync(FULLMASK, a0[2 * p], k);
                ap.y = __shfl_sync(FULLMASK, a0[2 * p + 1], k);
                w1[p] = ffma2(ap, d1, w1[p]);
                w2[p] = ffma2(ap, d2, w2[p]);
                w3[p] = ffma2(ap, d3, w3[p]);
                ef[p] = ffma2(ap, de, ef[p]);
            }
        }
#pragma unroll 4
        for (int k = 0; k < 32; k++) {
            float2 wa = Wa[(k + 32) * 32 + u];
            float2 wb = Wb[(k + 32) * 32 + u];
            float2 d1 = make_float2(wa.x, wa.x);
            float2 d2 = make_float2(wa.y, wa.y);
            float2 d3 = make_float2(wb.x, wb.x);
            float2 de = make_float2(wb.y, wb.y);
#pragma unroll
            for (int p = 0; p < 4; p++) {
                float2 ap;
                ap.x = __shfl_sync(FULLMASK, a1[2 * p], k);
                ap.y = __shfl_sync(FULLMASK, a1[2 * p + 1], k);
                w1[p] = ffma2(ap, d1, w1[p]);
                w2[p] = ffma2(ap, d2, w2[p]);
                w3[p] = ffma2(ap, d3, w3[p]);
                ef[p] = ffma2(ap, de, ef[p]);
            }
        }
#pragma unroll
        for (int j = 0; j < 8; j++) {
            int e = e0 + j;
            if (e >= E) break;
            int p = j >> 1;
            float W1 = (j & 1) ? w1[p].y : w1[p].x;
            float W2 = (j & 1) ? w2[p].y : w2[p].x;
            float W3 = (j & 1) ? w3[p].y : w3[p].x;
            float EF = (j & 1) ? ef[p].y : ef[p].x;
            outEF[(size_t)e * 32 + u] = EF;
            float C = geo[j].x, vx = geo[j].y, vy = geo[j].z, vz = geo[j].w;
            float zc = zj[j] * C;
            float fI = zc * W1;
            float pp = zc * W2;
            float qq = zc * W3;
            float* base = g_acc + ((size_t)dn[j] * 32 + u) * 12;
            red_add_v4(base,     fI,            pp * vx,       pp * vy,       pp * vz);
            red_add_v4(base + 4, qq * vx * vx,  qq * vy * vy,  qq * vz * vz,  qq * vx * vy);
            red_add_v2(base + 8, qq * vx * vz,  qq * vy * vz);
        }
    }
}

// ---------------- node epilogue ----------------
__global__ __launch_bounds__(256) void node_kernel(
    const float* __restrict__ Ws1, const float* __restrict__ bs1,
    const float* __restrict__ Ws2, const float* __restrict__ bs2,
    const float* __restrict__ Wt0, const float* __restrict__ Wt1, const float* __restrict__ Wt2,
    const float* __restrict__ lng, const float* __restrict__ lnb,
    float* __restrict__ outX, int N)
{
    __shared__ float Ws1s[32 * 64];
    __shared__ float Ws2s[64 * 96];
    __shared__ float Wt0s[32 * 32], Wt1s[32 * 32], Wt2s[32 * 32];
    __shared__ float bs1s[64], bs2s[96], lngs[32], lnbs[32];
    __shared__ float wbuf[8][64];
    int tid = threadIdx.x;
    for (int i = tid; i < 32 * 64; i += 256) Ws1s[i] = Ws1[i];
    for (int i = tid; i < 64 * 96; i += 256) Ws2s[i] = Ws2[i];
    for (int i = tid; i < 32 * 32; i += 256) { Wt0s[i] = Wt0[i]; Wt1s[i] = Wt1[i]; Wt2s[i] = Wt2[i]; }
    if (tid < 64) bs1s[tid] = bs1[tid];
    if (tid < 96) bs2s[tid] = bs2[tid];
    if (tid < 32) { lngs[tid] = lng[tid]; lnbs[tid] = lnb[tid]; }
    __syncthreads();
    const int u = tid & 31, w = tid >> 5;
    float* wb = wbuf[w];
    int gw = blockIdx.x * 8 + w, nw = gridDim.x * 8;
    for (int n = gw; n < N; n += nw) {
        const float* base = g_acc + ((size_t)n * 32 + u) * 12;
        float4 A0 = *reinterpret_cast<const float4*>(base);
        float4 A1 = *reinterpret_cast<const float4*>(base + 4);
        float2 A2 = *reinterpret_cast<const float2*>(base + 8);
        float sI = A0.x, wx = A0.y, wy = A0.z, wz = A0.w;
        float Mxx = A1.x, Myy = A1.y, Mzz = A1.z, Mxy = A1.w, Mxz = A2.x, Myz = A2.y;
        float trM = Mxx + Myy + Mzz;
        float dg = sI - trM * (1.f / 3.f);
        float t00 = dg + Mxx, t11 = dg + Myy, t22 = dg + Mzz;
        float nr = t00 * t00 + t11 * t11 + t22 * t22
                 + 2.f * (Mxy * Mxy + wz * wz + Mxz * Mxz + wy * wy + Myz * Myz + wx * wx);
        float s = nr;
#pragma unroll
        for (int o = 16; o; o >>= 1) s += __shfl_xor_sync(FULLMASK, s, o);
        float mu = s * (1.f / 32.f);
        float dv = nr - mu;
        float v2 = dv * dv;
#pragma unroll
        for (int o = 16; o; o >>= 1) v2 += __shfl_xor_sync(FULLMASK, v2, o);
        float y = dv * rsqrtf(v2 * (1.f / 32.f) + 1e-5f) * lngs[u] + lnbs[u];
        wb[u] = y;
        __syncwarp();
        float h1a = bs1s[u], h1b = bs1s[u + 32];
#pragma unroll 8
        for (int k = 0; k < 32; k++) {
            float t = wb[k];
            h1a = fmaf(t, Ws1s[k * 64 + u], h1a);
            h1b = fmaf(t, Ws1s[k * 64 + u + 32], h1b);
        }
        h1a = h1a / (1.f + __expf(-h1a));
        h1b = h1b / (1.f + __expf(-h1b));
        __syncwarp();
        wb[u] = h1a; wb[u + 32] = h1b;
        __syncwarp();
        float s0 = bs2s[3 * u], s1 = bs2s[3 * u + 1], s2 = bs2s[3 * u + 2];
#pragma unroll 8
        for (int k = 0; k < 64; k++) {
            float t = wb[k];
            s0 = fmaf(t, Ws2s[k * 96 + 3 * u], s0);
            s1 = fmaf(t, Ws2s[k * 96 + 3 * u + 1], s1);
            s2 = fmaf(t, Ws2s[k * 96 + 3 * u + 2], s2);
        }
        s0 = s0 / (1.f + __expf(-s0));
        s1 = s1 / (1.f + __expf(-s1));
        s2 = s2 / (1.f + __expf(-s2));
        float pI = 0, px = 0, py = 0, pz = 0, pxx = 0, pyy = 0, pzz = 0, pxy = 0, pxz = 0, pyz = 0;
#pragma unroll 4
        for (int k = 0; k < 32; k++) {
            float w0v = Wt0s[k * 32 + u], w1v = Wt1s[k * 32 + u], w2v = Wt2s[k * 32 + u];
            pI  = fmaf(__shfl_sync(FULLMASK, sI,  k), w0v, pI);
            px  = fmaf(__shfl_sync(FULLMASK, wx,  k), w1v, px);
            py  = fmaf(__shfl_sync(FULLMASK, wy,  k), w1v, py);
            pz  = fmaf(__shfl_sync(FULLMASK, wz,  k), w1v, pz);
            pxx = fmaf(__shfl_sync(FULLMASK, Mxx, k), w2v, pxx);
            pyy = fmaf(__shfl_sync(FULLMASK, Myy, k), w2v, pyy);
            pzz = fmaf(__shfl_sync(FULLMASK, Mzz, k), w2v, pzz);
            pxy = fmaf(__shfl_sync(FULLMASK, Mxy, k), w2v, pxy);
            pxz = fmaf(__shfl_sync(FULLMASK, Mxz, k), w2v, pxz);
            pyz = fmaf(__shfl_sync(FULLMASK, Myz, k), w2v, pyz);
        }
        float t3 = (pxx + pyy + pzz) * (1.f / 3.f);
        float* o = outX + ((size_t)n * 32 + u) * 9;
        o[0] =  s0 * pI + s2 * (pxx - t3);
        o[1] = -s1 * pz + s2 * pxy;
        o[2] =  s1 * py + s2 * pxz;
        o[3] =  s1 * pz + s2 * pxy;
        o[4] =  s0 * pI + s2 * (pyy - t3);
        o[5] = -s1 * px + s2 * pyz;
        o[6] = -s1 * py + s2 * pxz;
        o[7] =  s1 * px + s2 * pyz;
        o[8] =  s0 * pI + s2 * (pzz - t3);
        __syncwarp();
    }
}

extern "C" void kernel_launch(void* const* d_in, const int* in_sizes, int n_in,
                              void* d_out, int out_size) {
    (void)n_in; (void)out_size;
    const int*   node_type = (const int*)d_in[0];
    const float* edge_attr = (const float*)d_in[1];
    const float* bond_dist = (const float*)d_in[2];
    const float* bond_vec  = (const float*)d_in[3];
    const int*   src = (const int*)d_in[4];
    const int*   dst = (const int*)d_in[5];
    const float* emb = (const float*)d_in[6];
    const float* Wd1 = (const float*)d_in[7];  const float* bd1 = (const float*)d_in[8];
    const float* Wd2 = (const float*)d_in[9];  const float* bd2 = (const float*)d_in[10];
    const float* Wd3 = (const float*)d_in[11]; const float* bd3 = (const float*)d_in[12];
    const float* We2 = (const float*)d_in[13]; const float* be2 = (const float*)d_in[14];
    const float* We3 = (const float*)d_in[15]; const float* be3 = (const float*)d_in[16];
    const float* Wt0 = (const float*)d_in[17];
    const float* Wt1 = (const float*)d_in[18];
    const float* Wt2 = (const float*)d_in[19];
    const float* Ws1 = (const float*)d_in[20]; const float* bs1 = (const float*)d_in[21];
    const float* Ws2 = (const float*)d_in[22]; const float* bs2 = (const float*)d_in[23];
    const float* lng = (const float*)d_in[24]; const float* lnb = (const float*)d_in[25];

    int N = in_sizes[0];
    int E = in_sizes[2];
    int ntypes = in_sizes[6] / 32;
    float* outX  = (float*)d_out;
    float* outEF = outX + (size_t)N * 32 * 9;

    zh_kernel<<<ntypes, 64>>>(emb, We2, ntypes);
    ptab_kernel<<<(ntypes * ntypes + 7) / 8, 256>>>(be2, ntypes);
    prep_kernel<<<1024, 256>>>(src, dst, node_type, bond_dist, bond_vec, N, E, ntypes);
    edge_kernel<<<592, 256>>>(edge_attr, dst, Wd1, bd1, Wd2, bd2, Wd3, bd3,
                              We3, be3, outEF, E);
    node_kernel<<<592, 256>>>(Ws1, bs1, Ws2, bs2, Wt0, Wt1, Wt2, lng, lnb, outX, N);
}